// round 8
// baseline (speedup 1.0000x reference)
#include <cuda_runtime.h>

#define Bn 32
#define Cn 32
#define Gn 4096
#define Nn 16384
#define Hn 64
#define CG_BLOCKS ((Bn * Gn) / 256)       // 512 cellgemm blocks

typedef unsigned long long u64;

// slot -> cell index (materialized by scatter; replaces searchsorted)
__device__ int g_idx[Bn * Nn];
// per-cell layer-1 pre-activations, hp-pair interleaved:
// g_A2[(b*16 + hp2)*Gn + cell] = { pk(pre[4hp2],pre[4hp2+1]), pk(pre[4hp2+2],pre[4hp2+3]) }
__device__ ulonglong2 g_A2[(size_t)Bn * 16 * Gn];   // 32 MB

// ---- packed f32x2 helpers --------------------------------------------------
static __device__ __forceinline__ u64 pk(float lo, float hi) {
    u64 r; asm("mov.b64 %0, {%1, %2};" : "=l"(r) : "f"(lo), "f"(hi)); return r;
}
static __device__ __forceinline__ void upk(float& lo, float& hi, u64 v) {
    asm("mov.b64 {%0, %1}, %2;" : "=f"(lo), "=f"(hi) : "l"(v));
}
static __device__ __forceinline__ u64 fma2(u64 a, u64 b, u64 c) {
    u64 d; asm("fma.rn.f32x2 %0, %1, %2, %3;" : "=l"(d) : "l"(a), "l"(b), "l"(c));
    return d;
}

// ---- weight blob (staged in device mem, executed from constant mem) --------
struct __align__(16) WBlob {
    u64 w1T[Cn][32];     // [c][hp] = pk(W1[2hp][c], W1[2hp+1][c])
    u64 b1p[32];         // pk(b1[2hp], b1[2hp+1])
    u64 w32p[32];        // pk(W1[2hp][32], W1[2hp+1][32])
    u64 w33p[32];        // pk(W1[2hp][33], W1[2hp+1][33])
    u64 w2xp[32];        // pk(W2[0][2hp], W2[0][2hp+1])
    u64 w2yp[32];
    u64 w2zp[32];
    float b2v[4];
};
__device__   WBlob g_blob;
__constant__ WBlob c_blob;

// ---------------------------------------------------------------------------
// Kernel 0: blocks 0..4: weight transform. blocks 5..36: cumsum + scatter.
// (scatter doesn't need weights, so it overlaps the transform)
// ---------------------------------------------------------------------------
__global__ __launch_bounds__(256) void prep_kernel(const int* __restrict__ counts,
                                                   const float* __restrict__ W1,
                                                   const float* __restrict__ b1,
                                                   const float* __restrict__ W2,
                                                   const float* __restrict__ b2)
{
    const int t = threadIdx.x;

    if (blockIdx.x < 4) {
        const int i = blockIdx.x * 256 + t;      // 1024 w1T entries
        const int c = i >> 5, hp = i & 31;
        g_blob.w1T[c][hp] = pk(W1[(2 * hp) * 34 + c], W1[(2 * hp + 1) * 34 + c]);
        return;
    }
    if (blockIdx.x == 4) {
        if (t < 32) {
            g_blob.b1p[t]  = pk(b1[2 * t], b1[2 * t + 1]);
            g_blob.w32p[t] = pk(W1[(2 * t) * 34 + 32], W1[(2 * t + 1) * 34 + 32]);
            g_blob.w33p[t] = pk(W1[(2 * t) * 34 + 33], W1[(2 * t + 1) * 34 + 33]);
            g_blob.w2xp[t] = pk(W2[2 * t],            W2[2 * t + 1]);
            g_blob.w2yp[t] = pk(W2[Hn + 2 * t],       W2[Hn + 2 * t + 1]);
            g_blob.w2zp[t] = pk(W2[2 * Hn + 2 * t],   W2[2 * Hn + 2 * t + 1]);
        }
        if (t < 3) g_blob.b2v[t] = b2[t];
        if (t == 3) g_blob.b2v[3] = 0.f;
        return;
    }

    // ---- cumsum + scatter for one batch ----
    const int b = blockIdx.x - 5;
    __shared__ int wsum[8];
    const int lane = t & 31;
    const int w    = t >> 5;
    const int base = t * 16;                     // 16 cells per thread

    int local[16];
    int s = 0;
#pragma unroll
    for (int i = 0; i < 16; i++) {
        s += counts[b * Gn + base + i];
        local[i] = s;
    }
    int v = s;
#pragma unroll
    for (int d = 1; d < 32; d <<= 1) {
        int u = __shfl_up_sync(0xffffffff, v, d);
        if (lane >= d) v += u;
    }
    if (lane == 31) wsum[w] = v;
    __syncthreads();
    int woff = 0;
    for (int i = 0; i < w; i++) woff += wsum[i];
    const int excl = woff + v - s;

    int* gi = g_idx + b * Nn;
    int start = excl;
#pragma unroll
    for (int i = 0; i < 16; i++) {
        const int end = excl + local[i];
        const int cell = base + i;
        for (int j = start; j < end; j++) gi[j] = cell;
        start = end;
    }
}

// ---------------------------------------------------------------------------
// Kernel 1: per-cell layer-1 GEMM, lane = cell, weights via uniform constant.
// ---------------------------------------------------------------------------
__global__ __launch_bounds__(256) void cellgemm_kernel(const float* __restrict__ x)
{
    const int gid  = blockIdx.x * 256 + threadIdx.x;   // covers Bn*Gn
    const int b    = gid >> 12;                        // / Gn
    const int cell = gid & (Gn - 1);

    u64 acc[32];
#pragma unroll
    for (int hp = 0; hp < 32; hp++) acc[hp] = c_blob.b1p[hp];

    const float* xb = x + (size_t)b * Cn * Gn + cell;
#pragma unroll 4
    for (int c = 0; c < Cn; c++) {
        float xv = __ldg(xb + c * Gn);
        u64 xp = pk(xv, xv);
#pragma unroll
        for (int hp = 0; hp < 32; hp++)
            acc[hp] = fma2(c_blob.w1T[c][hp], xp, acc[hp]);
    }

    // 16 coalesced STG.128 (hp-pair interleaved layout)
    ulonglong2* Ab = g_A2 + (size_t)b * 16 * Gn + cell;
#pragma unroll
    for (int hp2 = 0; hp2 < 16; hp2++)
        Ab[hp2 * Gn] = make_ulonglong2(acc[2 * hp2], acc[2 * hp2 + 1]);
}

// ---------------------------------------------------------------------------
// Kernel 2: per-point tail: idx lookup + 16x LDG.128 A gather + tiny MLP.
// ---------------------------------------------------------------------------
__global__ __launch_bounds__(256) void mlp_kernel(
    const float* __restrict__ b_rnd,   // (B, 2, N)
    const float* __restrict__ grid_o,  // (3, G)
    float* __restrict__ out,           // (B, 3, N)
    float* __restrict__ reg_out)       // (B, N)
{
    const int gid = blockIdx.x * 256 + threadIdx.x;  // covers Bn*Nn
    const int b = gid >> 14;                         // / Nn
    const int j = gid & (Nn - 1);

    const int idx = __ldg(g_idx + b * Nn + j);

    // gather 32 packed pre-activation pairs via 16 LDG.128
    u64 a2[32];
    const ulonglong2* Ab = g_A2 + (size_t)b * 16 * Gn + idx;
#pragma unroll
    for (int hp2 = 0; hp2 < 16; hp2++) {
        ulonglong2 vv = __ldg(Ab + hp2 * Gn);
        a2[2 * hp2]     = vv.x;
        a2[2 * hp2 + 1] = vv.y;
    }

    const float* br = b_rnd + (size_t)b * 2 * Nn;
    const float r0 = br[j], r1 = br[Nn + j];
    const u64 rp0 = pk(r0, r0), rp1 = pk(r1, r1);

    u64 oX2 = 0ull, oY2 = 0ull, oZ2 = 0ull;
#pragma unroll
    for (int hp = 0; hp < 32; hp++) {
        u64 pre = fma2(c_blob.w32p[hp], rp0, a2[hp]);
        pre     = fma2(c_blob.w33p[hp], rp1, pre);
        float plo, phi;
        upk(plo, phi, pre);
        plo = fmaxf(plo, 0.f);
        phi = fmaxf(phi, 0.f);
        u64 act = pk(plo, phi);
        oX2 = fma2(c_blob.w2xp[hp], act, oX2);
        oY2 = fma2(c_blob.w2yp[hp], act, oY2);
        oZ2 = fma2(c_blob.w2zp[hp], act, oZ2);
    }

    float xl, xh, yl, yh, zl, zh;
    upk(xl, xh, oX2); upk(yl, yh, oY2); upk(zl, zh, oZ2);
    const float o0 = c_blob.b2v[0] + xl + xh;
    const float o1 = c_blob.b2v[1] + yl + yh;
    const float o2 = c_blob.b2v[2] + zl + zh;

    const float thr = 0.10825317547305482f;  // sqrt(3)/16
    const float nrm = sqrtf(o0 * o0 + o1 * o1 + o2 * o2);

    float* outb = out + (size_t)b * 3 * Nn;
    outb[j]          = o0 + __ldg(grid_o + idx);
    outb[Nn + j]     = o1 + __ldg(grid_o + Gn + idx);
    outb[2 * Nn + j] = o2 + __ldg(grid_o + 2 * Gn + idx);
    reg_out[b * Nn + j] = fmaxf(nrm - thr, 0.f);
}

extern "C" void kernel_launch(void* const* d_in, const int* in_sizes, int n_in,
                              void* d_out, int out_size)
{
    const float* x      = (const float*)d_in[0];
    const int*   counts = (const int*)  d_in[1];
    const float* b_rnd  = (const float*)d_in[2];
    const float* grid_o = (const float*)d_in[3];
    const float* W1     = (const float*)d_in[4];
    const float* b1     = (const float*)d_in[5];
    const float* W2     = (const float*)d_in[6];
    const float* b2     = (const float*)d_in[7];

    float* out     = (float*)d_out;              // (B, 3, N)
    float* reg_out = out + (size_t)Bn * 3 * Nn;  // (B, N)

    prep_kernel<<<5 + Bn, 256>>>(counts, W1, b1, W2, b2);

    void* c_addr = nullptr;
    void* g_addr = nullptr;
    cudaGetSymbolAddress(&c_addr, c_blob);
    cudaGetSymbolAddress(&g_addr, g_blob);
    cudaMemcpyAsync(c_addr, g_addr, sizeof(WBlob), cudaMemcpyDeviceToDevice);

    cellgemm_kernel<<<CG_BLOCKS, 256>>>(x);
    mlp_kernel<<<(Bn * Nn) / 256, 256>>>(b_rnd, grid_o, out, reg_out);
}

// round 9
// speedup vs baseline: 1.2402x; 1.2402x over previous
#include <cuda_runtime.h>

#define Bn 32
#define Cn 32
#define Gn 4096
#define Nn 16384
#define Hn 64
#define SCAT_BLOCKS Bn
#define CG_BLOCKS ((Bn * Gn) / 256)       // 512 cellgemm blocks

typedef unsigned long long u64;

// slot -> cell index (materialized by scatter; replaces searchsorted)
__device__ int g_idx[Bn * Nn];
// per-cell layer-1 pre-activations, hp-pair interleaved:
// g_A2[(b*16 + hp2)*Gn + cell] = { pk(pre[4hp2],..), pk(pre[4hp2+2],..) }
__device__ ulonglong2 g_A2[(size_t)Bn * 16 * Gn];   // 32 MB

// ---- packed f32x2 helpers --------------------------------------------------
static __device__ __forceinline__ u64 pk(float lo, float hi) {
    u64 r; asm("mov.b64 %0, {%1, %2};" : "=l"(r) : "f"(lo), "f"(hi)); return r;
}
static __device__ __forceinline__ void upk(float& lo, float& hi, u64 v) {
    asm("mov.b64 {%0, %1}, %2;" : "=f"(lo), "=f"(hi) : "l"(v));
}
static __device__ __forceinline__ u64 fma2(u64 a, u64 b, u64 c) {
    u64 d; asm("fma.rn.f32x2 %0, %1, %2, %3;" : "=l"(d) : "l"(a), "l"(b), "l"(c));
    return d;
}

// ---- weight blob: lives in constant space, written in-place by wtrans ------
struct __align__(16) WBlob {
    u64 w1T[Cn][32];     // [c][hp] = pk(W1[2hp][c], W1[2hp+1][c])
    u64 b1p[32];         // pk(b1[2hp], b1[2hp+1])
    u64 w32p[32];        // pk(W1[2hp][32], W1[2hp+1][32])
    u64 w33p[32];        // pk(W1[2hp][33], W1[2hp+1][33])
    u64 w2xp[32];        // pk(W2[0][2hp], W2[0][2hp+1])
    u64 w2yp[32];
    u64 w2zp[32];
    float b2v[4];
};
__constant__ WBlob c_blob;

// ---------------------------------------------------------------------------
// Kernel 0: weight transform (5 blocks), writing DIRECTLY into constant space.
// Consumers launch strictly after; const caches are cold per launch.
// ---------------------------------------------------------------------------
__global__ __launch_bounds__(256) void wtrans_kernel(WBlob* __restrict__ blob,
                                                     const float* __restrict__ W1,
                                                     const float* __restrict__ b1,
                                                     const float* __restrict__ W2,
                                                     const float* __restrict__ b2)
{
    const int t = threadIdx.x;
    if (blockIdx.x < 4) {
        const int i = blockIdx.x * 256 + t;      // 1024 w1T entries
        const int c = i >> 5, hp = i & 31;
        blob->w1T[c][hp] = pk(W1[(2 * hp) * 34 + c], W1[(2 * hp + 1) * 34 + c]);
        return;
    }
    if (t < 32) {
        blob->b1p[t]  = pk(b1[2 * t], b1[2 * t + 1]);
        blob->w32p[t] = pk(W1[(2 * t) * 34 + 32], W1[(2 * t + 1) * 34 + 32]);
        blob->w33p[t] = pk(W1[(2 * t) * 34 + 33], W1[(2 * t + 1) * 34 + 33]);
        blob->w2xp[t] = pk(W2[2 * t],            W2[2 * t + 1]);
        blob->w2yp[t] = pk(W2[Hn + 2 * t],       W2[Hn + 2 * t + 1]);
        blob->w2zp[t] = pk(W2[2 * Hn + 2 * t],   W2[2 * Hn + 2 * t + 1]);
    }
    if (t < 3) blob->b2v[t] = b2[t];
    if (t == 3) blob->b2v[3] = 0.f;
}

// ---------------------------------------------------------------------------
// Kernel 1 (fused): blocks [0, SCAT_BLOCKS): cumsum + direct index scatter.
//                   blocks [SCAT_BLOCKS, +CG_BLOCKS): per-cell layer-1 GEMM.
// Scatter blocks first so wave 1 overlaps both roles.
// ---------------------------------------------------------------------------
__global__ __launch_bounds__(256) void fused_kernel(const float* __restrict__ x,
                                                    const int* __restrict__ counts)
{
    const int t = threadIdx.x;

    if (blockIdx.x < SCAT_BLOCKS) {
        // ---- cumsum + scatter for one batch ----
        const int b = blockIdx.x;
        __shared__ int wsum[8];
        const int lane = t & 31;
        const int w    = t >> 5;
        const int base = t * 16;                 // 16 cells per thread

        int local[16];
        int s = 0;
#pragma unroll
        for (int i = 0; i < 16; i++) {
            s += counts[b * Gn + base + i];
            local[i] = s;
        }
        int v = s;
#pragma unroll
        for (int d = 1; d < 32; d <<= 1) {
            int u = __shfl_up_sync(0xffffffff, v, d);
            if (lane >= d) v += u;
        }
        if (lane == 31) wsum[w] = v;
        __syncthreads();
        int woff = 0;
        for (int i = 0; i < w; i++) woff += wsum[i];
        const int excl = woff + v - s;

        int* gi = g_idx + b * Nn;
        int start = excl;
#pragma unroll
        for (int i = 0; i < 16; i++) {
            const int end = excl + local[i];
            const int cell = base + i;
            for (int j = start; j < end; j++) gi[j] = cell;
            start = end;
        }
        return;
    }

    // ---- per-cell layer-1 GEMM, lane = cell, weights via uniform constant --
    const int gid  = (blockIdx.x - SCAT_BLOCKS) * 256 + t;   // covers Bn*Gn
    const int b    = gid >> 12;                              // / Gn
    const int cell = gid & (Gn - 1);

    u64 acc[32];
#pragma unroll
    for (int hp = 0; hp < 32; hp++) acc[hp] = c_blob.b1p[hp];

    const float* xb = x + (size_t)b * Cn * Gn + cell;
#pragma unroll 4
    for (int c = 0; c < Cn; c++) {
        float xv = __ldg(xb + c * Gn);
        u64 xp = pk(xv, xv);
#pragma unroll
        for (int hp = 0; hp < 32; hp++)
            acc[hp] = fma2(c_blob.w1T[c][hp], xp, acc[hp]);
    }

    // 16 coalesced STG.128 (hp-pair interleaved layout)
    ulonglong2* Ab = g_A2 + (size_t)b * 16 * Gn + cell;
#pragma unroll
    for (int hp2 = 0; hp2 < 16; hp2++)
        Ab[hp2 * Gn] = make_ulonglong2(acc[2 * hp2], acc[2 * hp2 + 1]);
}

// ---------------------------------------------------------------------------
// Kernel 2: per-point tail: idx lookup + 16x LDG.128 A gather + tiny MLP.
// 512 threads/block to halve CTA count.
// ---------------------------------------------------------------------------
__global__ __launch_bounds__(512) void mlp_kernel(
    const float* __restrict__ b_rnd,   // (B, 2, N)
    const float* __restrict__ grid_o,  // (3, G)
    float* __restrict__ out,           // (B, 3, N)
    float* __restrict__ reg_out)       // (B, N)
{
    const int gid = blockIdx.x * 512 + threadIdx.x;  // covers Bn*Nn
    const int b = gid >> 14;                         // / Nn
    const int j = gid & (Nn - 1);

    const int idx = __ldg(g_idx + b * Nn + j);

    // gather 32 packed pre-activation pairs via 16 LDG.128
    u64 a2[32];
    const ulonglong2* Ab = g_A2 + (size_t)b * 16 * Gn + idx;
#pragma unroll
    for (int hp2 = 0; hp2 < 16; hp2++) {
        ulonglong2 vv = __ldg(Ab + hp2 * Gn);
        a2[2 * hp2]     = vv.x;
        a2[2 * hp2 + 1] = vv.y;
    }

    const float* br = b_rnd + (size_t)b * 2 * Nn;
    const float r0 = br[j], r1 = br[Nn + j];
    const u64 rp0 = pk(r0, r0), rp1 = pk(r1, r1);

    u64 oX2 = 0ull, oY2 = 0ull, oZ2 = 0ull;
#pragma unroll
    for (int hp = 0; hp < 32; hp++) {
        u64 pre = fma2(c_blob.w32p[hp], rp0, a2[hp]);
        pre     = fma2(c_blob.w33p[hp], rp1, pre);
        float plo, phi;
        upk(plo, phi, pre);
        plo = fmaxf(plo, 0.f);
        phi = fmaxf(phi, 0.f);
        u64 act = pk(plo, phi);
        oX2 = fma2(c_blob.w2xp[hp], act, oX2);
        oY2 = fma2(c_blob.w2yp[hp], act, oY2);
        oZ2 = fma2(c_blob.w2zp[hp], act, oZ2);
    }

    float xl, xh, yl, yh, zl, zh;
    upk(xl, xh, oX2); upk(yl, yh, oY2); upk(zl, zh, oZ2);
    const float o0 = c_blob.b2v[0] + xl + xh;
    const float o1 = c_blob.b2v[1] + yl + yh;
    const float o2 = c_blob.b2v[2] + zl + zh;

    const float thr = 0.10825317547305482f;  // sqrt(3)/16
    const float nrm = sqrtf(o0 * o0 + o1 * o1 + o2 * o2);

    float* outb = out + (size_t)b * 3 * Nn;
    outb[j]          = o0 + __ldg(grid_o + idx);
    outb[Nn + j]     = o1 + __ldg(grid_o + Gn + idx);
    outb[2 * Nn + j] = o2 + __ldg(grid_o + 2 * Gn + idx);
    reg_out[b * Nn + j] = fmaxf(nrm - thr, 0.f);
}

extern "C" void kernel_launch(void* const* d_in, const int* in_sizes, int n_in,
                              void* d_out, int out_size)
{
    const float* x      = (const float*)d_in[0];
    const int*   counts = (const int*)  d_in[1];
    const float* b_rnd  = (const float*)d_in[2];
    const float* grid_o = (const float*)d_in[3];
    const float* W1     = (const float*)d_in[4];
    const float* b1     = (const float*)d_in[5];
    const float* W2     = (const float*)d_in[6];
    const float* b2     = (const float*)d_in[7];

    float* out     = (float*)d_out;              // (B, 3, N)
    float* reg_out = out + (size_t)Bn * 3 * Nn;  // (B, N)

    void* c_addr = nullptr;
    cudaGetSymbolAddress(&c_addr, c_blob);

    wtrans_kernel<<<5, 256>>>((WBlob*)c_addr, W1, b1, W2, b2);
    fused_kernel<<<SCAT_BLOCKS + CG_BLOCKS, 256>>>(x, counts);
    mlp_kernel<<<(Bn * Nn) / 512, 512>>>(b_rnd, grid_o, out, reg_out);
}